// round 1
// baseline (speedup 1.0000x reference)
#include <cuda_runtime.h>
#include <math.h>

#define Bc 64
#define Sc 2048
#define Hc 512
#define Kc 1024
#define SCC 16
#define SCHUNK (Sc/SCC)   // 128

// Scratch (no allocations allowed in kernel_launch)
__device__ float g_q[Bc*Hc];            // 128 KB
__device__ float g_scores[Bc*Sc];       // 512 KB
__device__ float g_part[SCC*Bc*Kc];     // 4 MB

// Accurate-enough tanh: tanh(x) = 1 - 2/(exp(2x)+1).
// __expf is ~2 ulp, so overall error ~1e-6 (vs 1e-3 tolerance).
__device__ __forceinline__ float fast_tanhf(float x) {
    float e = __expf(2.0f * x);
    return 1.0f - __fdividef(2.0f, e + 1.0f);
}

// ---------------------------------------------------------------------------
// K1: q[b,h] = sum_e query[b,e] * W_q[h,e]
// grid (Hc/8, Bc), block 256 (8 warps). Warp w computes h = bx*8+w.
// query row cached in smem; W_q row read coalesced as float4.
// ---------------------------------------------------------------------------
__global__ void qproj_kernel(const float* __restrict__ query,
                             const float* __restrict__ Wq) {
    __shared__ float sq[Hc];
    const int b = blockIdx.y;
    const int t = threadIdx.x;
    sq[t]       = query[b*Hc + t];
    sq[t + 256] = query[b*Hc + t + 256];
    __syncthreads();

    const int warp = t >> 5, lane = t & 31;
    const int h = blockIdx.x * 8 + warp;
    const float4* wrow = (const float4*)(Wq + (size_t)h * Hc);
    float acc = 0.0f;
#pragma unroll
    for (int i = 0; i < 4; i++) {
        float4 w = wrow[lane + 32*i];
        int e = (lane + 32*i) * 4;
        acc = fmaf(w.x, sq[e],   acc);
        acc = fmaf(w.y, sq[e+1], acc);
        acc = fmaf(w.z, sq[e+2], acc);
        acc = fmaf(w.w, sq[e+3], acc);
    }
#pragma unroll
    for (int o = 16; o; o >>= 1) acc += __shfl_xor_sync(0xffffffffu, acc, o);
    if (lane == 0) g_q[b*Hc + h] = acc;
}

// ---------------------------------------------------------------------------
// K2: scores[b,s] = sum_h tanh(q[b,h] + pk[b,s,h]) * v[h]
// grid Bc*Sc/8, block 256 (8 warps, warp per row). Each block stays within
// one b (2048 rows per b, 8 rows per block). q[b,:] and v cached in smem
// (keeps L2 traffic at the proj_key stream only).
// ---------------------------------------------------------------------------
__global__ void score_kernel(const float* __restrict__ pk,
                             const float* __restrict__ v) {
    __shared__ float sq[Hc];
    __shared__ float sv[Hc];
    const int t = threadIdx.x;
    const int row0 = blockIdx.x * 8;
    const int b = row0 >> 11;               // S = 2048
    sq[t]       = g_q[b*Hc + t];
    sq[t + 256] = g_q[b*Hc + t + 256];
    sv[t]       = v[t];
    sv[t + 256] = v[t + 256];
    __syncthreads();

    const int warp = t >> 5, lane = t & 31;
    const int row = row0 + warp;
    const float4* p = (const float4*)(pk + (size_t)row * Hc);
    float acc = 0.0f;
#pragma unroll
    for (int i = 0; i < 4; i++) {
        float4 a = p[lane + 32*i];
        int e = (lane + 32*i) * 4;
        acc = fmaf(fast_tanhf(a.x + sq[e]),   sv[e],   acc);
        acc = fmaf(fast_tanhf(a.y + sq[e+1]), sv[e+1], acc);
        acc = fmaf(fast_tanhf(a.z + sq[e+2]), sv[e+2], acc);
        acc = fmaf(fast_tanhf(a.w + sq[e+3]), sv[e+3], acc);
    }
#pragma unroll
    for (int o = 16; o; o >>= 1) acc += __shfl_xor_sync(0xffffffffu, acc, o);
    if (lane == 0) g_scores[row] = acc;
}

// ---------------------------------------------------------------------------
// K3: masked softmax over s for each b. grid Bc, block 256, 8 values/thread.
// Writes alphas directly into d_out's alpha region.
// ---------------------------------------------------------------------------
__global__ void softmax_kernel(const int* __restrict__ mask,
                               float* __restrict__ alphas_out) {
    const int b = blockIdx.x, t = threadIdx.x;
    __shared__ float red[8];

    float vals[8];
    float mx = -INFINITY;
#pragma unroll
    for (int i = 0; i < 8; i++) {
        int s = t + 256*i;
        float x = g_scores[b*Sc + s];
        if (mask[b*Sc + s] == 0) x = -INFINITY;
        vals[i] = x;
        mx = fmaxf(mx, x);
    }
#pragma unroll
    for (int o = 16; o; o >>= 1) mx = fmaxf(mx, __shfl_xor_sync(0xffffffffu, mx, o));
    if ((t & 31) == 0) red[t >> 5] = mx;
    __syncthreads();
    mx = red[0];
#pragma unroll
    for (int i = 1; i < 8; i++) mx = fmaxf(mx, red[i]);

    float sum = 0.0f;
#pragma unroll
    for (int i = 0; i < 8; i++) {
        float e = __expf(vals[i] - mx);
        vals[i] = e;
        sum += e;
    }
#pragma unroll
    for (int o = 16; o; o >>= 1) sum += __shfl_xor_sync(0xffffffffu, sum, o);
    __syncthreads();
    if ((t & 31) == 0) red[t >> 5] = sum;
    __syncthreads();
    float tot = red[0];
#pragma unroll
    for (int i = 1; i < 8; i++) tot += red[i];
    float inv = 1.0f / tot;
#pragma unroll
    for (int i = 0; i < 8; i++)
        alphas_out[b*Sc + t + 256*i] = vals[i] * inv;
}

// ---------------------------------------------------------------------------
// K4: partial context. grid (SCC, Bc), block 256.
// CTA (c, b) accumulates over s in [c*128, (c+1)*128): thread t owns float4
// k-slot t (256 float4 = 1024 floats = full K). Coalesced 4 KB row reads.
// Deterministic: partials to scratch, no atomics.
// ---------------------------------------------------------------------------
__global__ void context_partial_kernel(const float* __restrict__ eh,
                                       const float* __restrict__ alphas) {
    __shared__ float sa[SCHUNK];
    const int c = blockIdx.x;
    const int b = blockIdx.y;
    const int t = threadIdx.x;
    if (t < SCHUNK) sa[t] = alphas[b*Sc + c*SCHUNK + t];
    __syncthreads();

    const float4* base = (const float4*)(eh + ((size_t)(b*Sc + c*SCHUNK)) * Kc);
    float4 acc = make_float4(0.f, 0.f, 0.f, 0.f);
#pragma unroll 4
    for (int s = 0; s < SCHUNK; s++) {
        float a = sa[s];
        float4 vv = base[(size_t)s * (Kc/4) + t];
        acc.x = fmaf(a, vv.x, acc.x);
        acc.y = fmaf(a, vv.y, acc.y);
        acc.z = fmaf(a, vv.z, acc.z);
        acc.w = fmaf(a, vv.w, acc.w);
    }
    ((float4*)g_part)[((size_t)c*Bc + b) * (Kc/4) + t] = acc;
}

// ---------------------------------------------------------------------------
// K5: reduce 16 partials -> context. grid Bc, block 256 (float4 per thread).
// ---------------------------------------------------------------------------
__global__ void context_reduce_kernel(float* __restrict__ ctx_out) {
    const int b = blockIdx.x, t = threadIdx.x;
    float4 acc = make_float4(0.f, 0.f, 0.f, 0.f);
#pragma unroll
    for (int c = 0; c < SCC; c++) {
        float4 v = ((const float4*)g_part)[((size_t)c*Bc + b) * (Kc/4) + t];
        acc.x += v.x; acc.y += v.y; acc.z += v.z; acc.w += v.w;
    }
    ((float4*)ctx_out)[(size_t)b * (Kc/4) + t] = acc;
}

// ---------------------------------------------------------------------------
extern "C" void kernel_launch(void* const* d_in, const int* in_sizes, int n_in,
                              void* d_out, int out_size) {
    const float* query    = (const float*)d_in[0]; // (B,1,H)
    const float* proj_key = (const float*)d_in[1]; // (B,S,H)
    const float* enc      = (const float*)d_in[2]; // (B,S,K)
    const int*   mask     = (const int*)  d_in[3]; // (B,1,S)
    const float* Wq       = (const float*)d_in[4]; // (H,H)
    const float* v        = (const float*)d_in[5]; // (H,)

    float* ctx    = (float*)d_out;              // (B,1,K)  = 65536 floats
    float* alphas = (float*)d_out + Bc*Kc;      // (B,1,S)  = 131072 floats

    qproj_kernel<<<dim3(Hc/8, Bc), 256>>>(query, Wq);
    score_kernel<<<(Bc*Sc)/8, 256>>>(proj_key, v);
    softmax_kernel<<<Bc, 256>>>(mask, alphas);
    context_partial_kernel<<<dim3(SCC, Bc), 256>>>(enc, alphas);
    context_reduce_kernel<<<Bc, 256>>>(ctx);
}

// round 2
// speedup vs baseline: 1.0525x; 1.0525x over previous
#include <cuda_runtime.h>
#include <math.h>

#define Bc 64
#define Sc 2048
#define Hc 512
#define Kc 1024
#define SCC 16
#define SCHUNK (Sc/SCC)   // 128

// Scratch (no allocations allowed in kernel_launch)
__device__ float g_q[Bc*Hc];            // 128 KB
__device__ float g_scores[Bc*Sc];       // 512 KB
__device__ float g_part[SCC*Bc*Kc];     // 4 MB

// tanh(x) = 1 - 2/(exp(2x)+1); __expf ~2ulp -> overall ~1e-6 error.
__device__ __forceinline__ float fast_tanhf(float x) {
    float e = __expf(2.0f * x);
    return 1.0f - __fdividef(2.0f, e + 1.0f);
}

#if defined(__CUDA_ARCH__) && (__CUDA_ARCH__ >= 900)
#define GRID_DEP_SYNC() cudaGridDependencySynchronize()
#else
#define GRID_DEP_SYNC()
#endif

// ---------------------------------------------------------------------------
// K1: q[b,h] = sum_e query[b,e] * W_q[h,e]
// grid (Hc/8, Bc), block 256 (warp per h). No upstream dependency.
// ---------------------------------------------------------------------------
__global__ void qproj_kernel(const float* __restrict__ query,
                             const float* __restrict__ Wq) {
    __shared__ float sq[Hc];
    const int b = blockIdx.y;
    const int t = threadIdx.x;
    sq[t]       = query[b*Hc + t];
    sq[t + 256] = query[b*Hc + t + 256];
    __syncthreads();

    const int warp = t >> 5, lane = t & 31;
    const int h = blockIdx.x * 8 + warp;
    const float4* wrow = (const float4*)(Wq + (size_t)h * Hc);
    float acc = 0.0f;
#pragma unroll
    for (int i = 0; i < 4; i++) {
        float4 w = wrow[lane + 32*i];
        int e = (lane + 32*i) * 4;
        acc = fmaf(w.x, sq[e],   acc);
        acc = fmaf(w.y, sq[e+1], acc);
        acc = fmaf(w.z, sq[e+2], acc);
        acc = fmaf(w.w, sq[e+3], acc);
    }
#pragma unroll
    for (int o = 16; o; o >>= 1) acc += __shfl_xor_sync(0xffffffffu, acc, o);
    if (lane == 0) g_q[b*Hc + h] = acc;
}

// ---------------------------------------------------------------------------
// K2: scores[b,s] = sum_h tanh(q[b,h] + pk[b,s,h]) * v[h]
// block 256 (8 warps), each warp handles 2 rows -> 16 rows/block, 8192 blocks.
// q[b,:], v in smem. pk streamed with __ldcs (evict-first: single use).
// ---------------------------------------------------------------------------
__global__ void score_kernel(const float* __restrict__ pk,
                             const float* __restrict__ v) {
    __shared__ float sq[Hc];
    __shared__ float sv[Hc];
    const int t = threadIdx.x;
    const int row0 = blockIdx.x * 16;
    const int b = row0 >> 11;               // S = 2048, blocks don't straddle b
    // v is a kernel input (no dependency)
    sv[t]       = v[t];
    sv[t + 256] = v[t + 256];
    GRID_DEP_SYNC();                        // wait for qproj's g_q
    sq[t]       = g_q[b*Hc + t];
    sq[t + 256] = g_q[b*Hc + t + 256];
    __syncthreads();

    const int warp = t >> 5, lane = t & 31;
    const int rowA = row0 + warp*2;
    const int rowB = rowA + 1;
    const float4* pA = (const float4*)(pk + (size_t)rowA * Hc);
    const float4* pB = (const float4*)(pk + (size_t)rowB * Hc);
    float accA = 0.0f, accB = 0.0f;
#pragma unroll
    for (int i = 0; i < 4; i++) {
        float4 a = __ldcs(pA + lane + 32*i);
        float4 c = __ldcs(pB + lane + 32*i);
        int e = (lane + 32*i) * 4;
        float q0 = sq[e], q1 = sq[e+1], q2 = sq[e+2], q3 = sq[e+3];
        float v0 = sv[e], v1 = sv[e+1], v2 = sv[e+2], v3 = sv[e+3];
        accA = fmaf(fast_tanhf(a.x + q0), v0, accA);
        accA = fmaf(fast_tanhf(a.y + q1), v1, accA);
        accA = fmaf(fast_tanhf(a.z + q2), v2, accA);
        accA = fmaf(fast_tanhf(a.w + q3), v3, accA);
        accB = fmaf(fast_tanhf(c.x + q0), v0, accB);
        accB = fmaf(fast_tanhf(c.y + q1), v1, accB);
        accB = fmaf(fast_tanhf(c.z + q2), v2, accB);
        accB = fmaf(fast_tanhf(c.w + q3), v3, accB);
    }
#pragma unroll
    for (int o = 16; o; o >>= 1) {
        accA += __shfl_xor_sync(0xffffffffu, accA, o);
        accB += __shfl_xor_sync(0xffffffffu, accB, o);
    }
    if (lane == 0) {
        g_scores[rowA] = accA;
        g_scores[rowB] = accB;
    }
}

// ---------------------------------------------------------------------------
// K3: masked softmax over s for each b. grid Bc, block 256, 8 values/thread.
// ---------------------------------------------------------------------------
__global__ void softmax_kernel(const int* __restrict__ mask,
                               float* __restrict__ alphas_out) {
    const int b = blockIdx.x, t = threadIdx.x;
    __shared__ float red[8];

    // mask is a kernel input (independent of score kernel)
    int m[8];
#pragma unroll
    for (int i = 0; i < 8; i++) m[i] = mask[b*Sc + t + 256*i];

    GRID_DEP_SYNC();                        // wait for g_scores

    float vals[8];
    float mx = -INFINITY;
#pragma unroll
    for (int i = 0; i < 8; i++) {
        float x = g_scores[b*Sc + t + 256*i];
        if (m[i] == 0) x = -INFINITY;
        vals[i] = x;
        mx = fmaxf(mx, x);
    }
#pragma unroll
    for (int o = 16; o; o >>= 1) mx = fmaxf(mx, __shfl_xor_sync(0xffffffffu, mx, o));
    if ((t & 31) == 0) red[t >> 5] = mx;
    __syncthreads();
    mx = red[0];
#pragma unroll
    for (int i = 1; i < 8; i++) mx = fmaxf(mx, red[i]);

    float sum = 0.0f;
#pragma unroll
    for (int i = 0; i < 8; i++) {
        float e = __expf(vals[i] - mx);
        vals[i] = e;
        sum += e;
    }
#pragma unroll
    for (int o = 16; o; o >>= 1) sum += __shfl_xor_sync(0xffffffffu, sum, o);
    __syncthreads();
    if ((t & 31) == 0) red[t >> 5] = sum;
    __syncthreads();
    float tot = red[0];
#pragma unroll
    for (int i = 1; i < 8; i++) tot += red[i];
    float inv = 1.0f / tot;
#pragma unroll
    for (int i = 0; i < 8; i++)
        alphas_out[b*Sc + t + 256*i] = vals[i] * inv;
}

// ---------------------------------------------------------------------------
// K4: partial context. grid (SCC, Bc), block 256.
// Thread t owns float4 k-slot t. eh streamed with __ldcs, full unroll for MLP.
// ---------------------------------------------------------------------------
__global__ void context_partial_kernel(const float* __restrict__ eh,
                                       const float* __restrict__ alphas) {
    __shared__ float sa[SCHUNK];
    const int c = blockIdx.x;
    const int b = blockIdx.y;
    const int t = threadIdx.x;

    GRID_DEP_SYNC();                        // wait for alphas (softmax output)
    if (t < SCHUNK) sa[t] = alphas[b*Sc + c*SCHUNK + t];
    __syncthreads();

    const float4* base = (const float4*)(eh + ((size_t)(b*Sc + c*SCHUNK)) * Kc)
                         + t;
    float4 acc = make_float4(0.f, 0.f, 0.f, 0.f);
#pragma unroll 8
    for (int s = 0; s < SCHUNK; s++) {
        float a = sa[s];
        float4 vv = __ldcs(base + (size_t)s * (Kc/4));
        acc.x = fmaf(a, vv.x, acc.x);
        acc.y = fmaf(a, vv.y, acc.y);
        acc.z = fmaf(a, vv.z, acc.z);
        acc.w = fmaf(a, vv.w, acc.w);
    }
    ((float4*)g_part)[((size_t)c*Bc + b) * (Kc/4) + t] = acc;
}

// ---------------------------------------------------------------------------
// K5: reduce 16 partials -> context. grid Bc, block 256 (float4 per thread).
// ---------------------------------------------------------------------------
__global__ void context_reduce_kernel(float* __restrict__ ctx_out) {
    const int b = blockIdx.x, t = threadIdx.x;
    GRID_DEP_SYNC();                        // wait for g_part
    float4 acc = make_float4(0.f, 0.f, 0.f, 0.f);
#pragma unroll
    for (int c = 0; c < SCC; c++) {
        float4 v = ((const float4*)g_part)[((size_t)c*Bc + b) * (Kc/4) + t];
        acc.x += v.x; acc.y += v.y; acc.z += v.z; acc.w += v.w;
    }
    ((float4*)ctx_out)[(size_t)b * (Kc/4) + t] = acc;
}

// ---------------------------------------------------------------------------
// Launch helper with programmatic stream serialization (PDL): dependent grid
// may be scheduled while the predecessor drains; consumers gate on
// cudaGridDependencySynchronize().
// ---------------------------------------------------------------------------
template <typename K, typename... Args>
static inline void launch_pdl(K kernel, dim3 grid, dim3 block, Args... args) {
    cudaLaunchAttribute attr[1];
    attr[0].id = cudaLaunchAttributeProgrammaticStreamSerialization;
    attr[0].val.programmaticStreamSerializationAllowed = 1;
    cudaLaunchConfig_t cfg;
    cfg.gridDim = grid;
    cfg.blockDim = block;
    cfg.dynamicSmemBytes = 0;
    cfg.stream = 0;
    cfg.attrs = attr;
    cfg.numAttrs = 1;
    cudaLaunchKernelEx(&cfg, kernel, args...);
}

extern "C" void kernel_launch(void* const* d_in, const int* in_sizes, int n_in,
                              void* d_out, int out_size) {
    const float* query    = (const float*)d_in[0]; // (B,1,H)
    const float* proj_key = (const float*)d_in[1]; // (B,S,H)
    const float* enc      = (const float*)d_in[2]; // (B,S,K)
    const int*   mask     = (const int*)  d_in[3]; // (B,1,S)
    const float* Wq       = (const float*)d_in[4]; // (H,H)
    const float* v        = (const float*)d_in[5]; // (H,)

    float* ctx    = (float*)d_out;              // (B,1,K)
    float* alphas = (float*)d_out + Bc*Kc;      // (B,1,S)

    qproj_kernel<<<dim3(Hc/8, Bc), 256>>>(query, Wq);
    launch_pdl(score_kernel,           dim3((Bc*Sc)/16), dim3(256), proj_key, v);
    launch_pdl(softmax_kernel,         dim3(Bc),         dim3(256), mask, alphas);
    launch_pdl(context_partial_kernel, dim3(SCC, Bc),    dim3(256), enc, (const float*)alphas);
    launch_pdl(context_reduce_kernel,  dim3(Bc),         dim3(256), ctx);
}